// round 6
// baseline (speedup 1.0000x reference)
#include <cuda_runtime.h>
#include <cstdint>
#include <cstddef>

#define NNODES   50000
#define EDGESMAX 800000
#define HDIM     256   // NUM_HEADS * OUT_DIM

// -------- scratch (static __device__ arrays; no allocation allowed) --------
__device__ float g_Q[(size_t)NNODES * HDIM];
__device__ float g_K[(size_t)NNODES * HDIM];
__device__ float g_V[(size_t)NNODES * HDIM];
__device__ int   g_deg[NNODES];        // zero-init at load; scan re-zeroes it
__device__ int   g_cursor[NNODES];
__device__ int   g_rowptr[NNODES + 1];
__device__ int   g_csr_src[EDGESMAX];

// side stream + fork/join events, created once at module load (host objects)
struct SideStream {
    cudaStream_t s;
    cudaEvent_t  fork, join;
    SideStream() {
        cudaStreamCreateWithFlags(&s, cudaStreamNonBlocking);
        cudaEventCreateWithFlags(&fork, cudaEventDisableTiming);
        cudaEventCreateWithFlags(&join, cudaEventDisableTiming);
    }
};
static SideStream g_ss;

__device__ __forceinline__ uint32_t f2tf32(float x) {
    uint32_t r;
    asm("cvt.rna.tf32.f32 %0, %1;" : "=r"(r) : "f"(x));
    return r;
}

// ---------------------------------------------------------------------------
// CSR build: histogram -> exclusive scan (seeds cursor, re-zeroes deg) -> scatter
// ---------------------------------------------------------------------------
__global__ void hist_kernel(const int* __restrict__ dst, int E) {
    int e = blockIdx.x * blockDim.x + threadIdx.x;
    if (e < E) atomicAdd(&g_deg[dst[e]], 1);
}

__global__ __launch_bounds__(1024) void scan_kernel(int n) {
    __shared__ int warp_sums[32];
    __shared__ int s_carry;
    const int tid  = threadIdx.x;
    const int lane = tid & 31;
    const int wid  = tid >> 5;
    if (tid == 0) s_carry = 0;
    __syncthreads();

    for (int base = 0; base < n; base += 1024) {
        int i = base + tid;
        int v = (i < n) ? g_deg[i] : 0;
        int x = v;
        #pragma unroll
        for (int off = 1; off < 32; off <<= 1) {
            int t = __shfl_up_sync(0xffffffffu, x, off);
            if (lane >= off) x += t;
        }
        if (lane == 31) warp_sums[wid] = x;
        __syncthreads();
        if (wid == 0) {
            int w = warp_sums[lane];
            #pragma unroll
            for (int off = 1; off < 32; off <<= 1) {
                int t = __shfl_up_sync(0xffffffffu, w, off);
                if (lane >= off) w += t;
            }
            warp_sums[lane] = w;
        }
        __syncthreads();
        int warp_off = (wid > 0) ? warp_sums[wid - 1] : 0;
        int excl = s_carry + x + warp_off - v;
        if (i < n) {
            g_rowptr[i] = excl;
            g_cursor[i] = excl;
            g_deg[i]    = 0;          // restore invariant for next call
        }
        __syncthreads();
        if (tid == 1023) s_carry += warp_sums[31];
        __syncthreads();
    }
    if (tid == 0) g_rowptr[n] = s_carry;
}

__global__ void scatter_kernel(const int* __restrict__ src,
                               const int* __restrict__ dst, int E) {
    int e = blockIdx.x * blockDim.x + threadIdx.x;
    if (e < E) {
        int pos = atomicAdd(&g_cursor[dst[e]], 1);
        g_csr_src[pos] = src[e];
    }
}

// ---------------------------------------------------------------------------
// Kernel 1: fused QKV projection.  TF32 mma m16n8k8, tile 128x128x32.
// ---------------------------------------------------------------------------
__global__ __launch_bounds__(256) void qkv_gemm(
    const float* __restrict__ h,
    const float* __restrict__ Wq, const float* __restrict__ bq,
    const float* __restrict__ Wk, const float* __restrict__ bk,
    const float* __restrict__ Wv, const float* __restrict__ bv,
    int Nrows)
{
    __shared__ uint32_t As[128 * 36];
    __shared__ uint32_t Bs[128 * 36];

    const int tid  = threadIdx.x;
    const int lane = tid & 31;
    const int warp = tid >> 5;
    const int wm = warp >> 2;
    const int wn = warp & 3;
    const int bm = blockIdx.x;
    const int bn = blockIdx.y;

    const float* W;  const float* bias;  float* target;
    if (bn < 2)      { W = Wq; bias = bq; target = g_Q; }
    else if (bn < 4) { W = Wk; bias = bk; target = g_K; }
    else             { W = Wv; bias = bv; target = g_V; }
    const int ncol0 = (bn & 1) * 128;

    float acc[4][4][4];
    #pragma unroll
    for (int i = 0; i < 4; i++)
        #pragma unroll
        for (int j = 0; j < 4; j++)
            #pragma unroll
            for (int k = 0; k < 4; k++) acc[i][j][k] = 0.0f;

    const int lr = tid >> 3;
    const int lc = (tid & 7) * 4;

    for (int kb = 0; kb < 256; kb += 32) {
        #pragma unroll
        for (int i = 0; i < 4; i++) {
            int r = lr + i * 32;
            int grow = bm * 128 + r;
            float4 v = make_float4(0.f, 0.f, 0.f, 0.f);
            if (grow < Nrows)
                v = *(const float4*)(h + (size_t)grow * 256 + kb + lc);
            uint32_t* s = &As[r * 36 + lc];
            s[0] = f2tf32(v.x); s[1] = f2tf32(v.y);
            s[2] = f2tf32(v.z); s[3] = f2tf32(v.w);
        }
        #pragma unroll
        for (int i = 0; i < 4; i++) {
            int r = lr + i * 32;
            float4 v = *(const float4*)(W + (size_t)(ncol0 + r) * 256 + kb + lc);
            uint32_t* s = &Bs[r * 36 + lc];
            s[0] = f2tf32(v.x); s[1] = f2tf32(v.y);
            s[2] = f2tf32(v.z); s[3] = f2tf32(v.w);
        }
        __syncthreads();

        #pragma unroll
        for (int ks = 0; ks < 4; ks++) {
            const int k0 = ks * 8;
            uint32_t a[4][4], b[4][2];
            #pragma unroll
            for (int mt = 0; mt < 4; mt++) {
                int r = wm * 64 + mt * 16 + (lane >> 2);
                int c = k0 + (lane & 3);
                a[mt][0] = As[r * 36 + c];
                a[mt][1] = As[(r + 8) * 36 + c];
                a[mt][2] = As[r * 36 + c + 4];
                a[mt][3] = As[(r + 8) * 36 + c + 4];
            }
            #pragma unroll
            for (int nt = 0; nt < 4; nt++) {
                int n = wn * 32 + nt * 8 + (lane >> 2);
                int c = k0 + (lane & 3);
                b[nt][0] = Bs[n * 36 + c];
                b[nt][1] = Bs[n * 36 + c + 4];
            }
            #pragma unroll
            for (int mt = 0; mt < 4; mt++)
                #pragma unroll
                for (int nt = 0; nt < 4; nt++)
                    asm volatile(
                        "mma.sync.aligned.m16n8k8.row.col.f32.tf32.tf32.f32 "
                        "{%0,%1,%2,%3}, {%4,%5,%6,%7}, {%8,%9}, {%0,%1,%2,%3};"
                        : "+f"(acc[mt][nt][0]), "+f"(acc[mt][nt][1]),
                          "+f"(acc[mt][nt][2]), "+f"(acc[mt][nt][3])
                        : "r"(a[mt][0]), "r"(a[mt][1]), "r"(a[mt][2]), "r"(a[mt][3]),
                          "r"(b[nt][0]), "r"(b[nt][1]));
        }
        __syncthreads();
    }

    #pragma unroll
    for (int mt = 0; mt < 4; mt++) {
        int r0 = wm * 64 + mt * 16 + (lane >> 2);
        #pragma unroll
        for (int nt = 0; nt < 4; nt++) {
            int c0 = wn * 32 + nt * 8 + (lane & 3) * 2;
            #pragma unroll
            for (int cc = 0; cc < 4; cc++) {
                int r = r0 + ((cc >= 2) ? 8 : 0);
                int c = c0 + (cc & 1);
                int grow = bm * 128 + r;
                if (grow < Nrows) {
                    int j = ncol0 + c;
                    target[(size_t)grow * 256 + j] = acc[mt][nt][cc] + bias[j];
                }
            }
        }
    }
}

// ---------------------------------------------------------------------------
// Kernel 2: single-pass fused attention.  One warp per destination node.
// ---------------------------------------------------------------------------
__global__ __launch_bounds__(256) void attn_fused(
    float* __restrict__ out, int n_nodes)
{
    const int node = (blockIdx.x * blockDim.x + threadIdx.x) >> 5;
    if (node >= n_nodes) return;
    const int lane = threadIdx.x & 31;
    const unsigned FULL = 0xffffffffu;
    const float inv = 0.17677669529663687f;   // 1/sqrt(32)

    const int beg = g_rowptr[node];
    const int end = g_rowptr[node + 1];

    const float4* Qr = (const float4*)(g_Q + (size_t)node * 256);
    const float4 q0 = Qr[lane];
    const float4 q1 = Qr[lane + 32];

    float4 acc0 = make_float4(0.f, 0.f, 0.f, 0.f);
    float4 acc1 = make_float4(0.f, 0.f, 0.f, 0.f);
    float z0 = 0.0f, z1 = 0.0f;

    for (int i = beg; i < end; i++) {
        const int s = g_csr_src[i];
        const float4* Kr = (const float4*)(g_K + (size_t)s * 256);
        const float4* Vr = (const float4*)(g_V + (size_t)s * 256);
        float4 k0 = Kr[lane];
        float4 k1 = Kr[lane + 32];
        float4 v0 = Vr[lane];
        float4 v1 = Vr[lane + 32];

        float p0 = k0.x * q0.x + k0.y * q0.y + k0.z * q0.z + k0.w * q0.w;
        float p1 = k1.x * q1.x + k1.y * q1.y + k1.z * q1.z + k1.w * q1.w;
        #pragma unroll
        for (int off = 4; off; off >>= 1) {
            p0 += __shfl_xor_sync(FULL, p0, off);
            p1 += __shfl_xor_sync(FULL, p1, off);
        }
        float sc0 = __expf(fminf(fmaxf(p0 * inv, -5.0f), 5.0f));
        float sc1 = __expf(fminf(fmaxf(p1 * inv, -5.0f), 5.0f));
        z0 += sc0;
        z1 += sc1;

        acc0.x += sc0 * v0.x; acc0.y += sc0 * v0.y;
        acc0.z += sc0 * v0.z; acc0.w += sc0 * v0.w;
        acc1.x += sc1 * v1.x; acc1.y += sc1 * v1.y;
        acc1.z += sc1 * v1.z; acc1.w += sc1 * v1.w;
    }

    const float rz0 = (z0 > 0.0f) ? 1.0f / z0 : 0.0f;
    const float rz1 = (z1 > 0.0f) ? 1.0f / z1 : 0.0f;
    acc0.x *= rz0; acc0.y *= rz0; acc0.z *= rz0; acc0.w *= rz0;
    acc1.x *= rz1; acc1.y *= rz1; acc1.z *= rz1; acc1.w *= rz1;

    float4* o = (float4*)(out + (size_t)node * 256);
    o[lane]      = acc0;
    o[lane + 32] = acc1;
}

// ---------------------------------------------------------------------------
extern "C" void kernel_launch(void* const* d_in, const int* in_sizes, int n_in,
                              void* d_out, int out_size)
{
    const float* h  = (const float*)d_in[0];
    const float* Wq = (const float*)d_in[1];
    const float* bq = (const float*)d_in[2];
    const float* Wk = (const float*)d_in[3];
    const float* bk = (const float*)d_in[4];
    const float* Wv = (const float*)d_in[5];
    const float* bv = (const float*)d_in[6];
    const int*   src = (const int*)d_in[7];
    const int*   dst = (const int*)d_in[8];
    float* out = (float*)d_out;

    const int N = in_sizes[0] / 256;   // 50000
    const int E = in_sizes[7];         // 800000

    // fork: CSR chain on side stream, GEMM on main stream (independent)
    cudaEventRecord(g_ss.fork, 0);
    cudaStreamWaitEvent(g_ss.s, g_ss.fork, 0);

    hist_kernel   <<<(E + 255) / 256, 256, 0, g_ss.s>>>(dst, E);
    scan_kernel   <<<1, 1024, 0, g_ss.s>>>(N);
    scatter_kernel<<<(E + 255) / 256, 256, 0, g_ss.s>>>(src, dst, E);

    dim3 grid((N + 127) / 128, 6);
    qkv_gemm<<<grid, 256>>>(h, Wq, bq, Wk, bk, Wv, bv, N);

    // join: attention needs both CSR and Q/K/V
    cudaEventRecord(g_ss.join, g_ss.s);
    cudaStreamWaitEvent(0, g_ss.join, 0);

    attn_fused<<<(N * 32 + 255) / 256, 256>>>(out, N);
}

// round 7
// speedup vs baseline: 1.3897x; 1.3897x over previous
#include <cuda_runtime.h>
#include <cstdint>
#include <cstddef>

#define NNODES   50000
#define EDGESMAX 800000
#define HDIM     256   // NUM_HEADS * OUT_DIM

// -------- scratch (static __device__ arrays; no allocation allowed) --------
__device__ float g_Q[(size_t)NNODES * HDIM];
__device__ float g_K[(size_t)NNODES * HDIM];
__device__ float g_V[(size_t)NNODES * HDIM];
__device__ int   g_deg[NNODES];        // zero-init at load; scan re-zeroes it
__device__ int   g_cursor[NNODES];
__device__ int   g_rowptr[NNODES + 1];
__device__ int   g_csr_src[EDGESMAX];

__device__ __forceinline__ uint32_t f2tf32(float x) {
    uint32_t r;
    asm("cvt.rna.tf32.f32 %0, %1;" : "=r"(r) : "f"(x));
    return r;
}

__device__ __forceinline__ void cp_async16(uint32_t saddr, const void* gptr, int src_bytes) {
    asm volatile("cp.async.cg.shared.global [%0], [%1], 16, %2;"
                 :: "r"(saddr), "l"(gptr), "r"(src_bytes));
}

// ---------------------------------------------------------------------------
// CSR build: histogram -> exclusive scan (seeds cursor, re-zeroes deg) -> scatter
// ---------------------------------------------------------------------------
__global__ void hist_kernel(const int* __restrict__ dst, int E) {
    int e = blockIdx.x * blockDim.x + threadIdx.x;
    if (e < E) atomicAdd(&g_deg[dst[e]], 1);
}

__global__ __launch_bounds__(1024) void scan_kernel(int n) {
    __shared__ int warp_sums[32];
    __shared__ int s_carry;
    const int tid  = threadIdx.x;
    const int lane = tid & 31;
    const int wid  = tid >> 5;
    if (tid == 0) s_carry = 0;
    __syncthreads();

    for (int base = 0; base < n; base += 1024) {
        int i = base + tid;
        int v = (i < n) ? g_deg[i] : 0;
        int x = v;
        #pragma unroll
        for (int off = 1; off < 32; off <<= 1) {
            int t = __shfl_up_sync(0xffffffffu, x, off);
            if (lane >= off) x += t;
        }
        if (lane == 31) warp_sums[wid] = x;
        __syncthreads();
        if (wid == 0) {
            int w = warp_sums[lane];
            #pragma unroll
            for (int off = 1; off < 32; off <<= 1) {
                int t = __shfl_up_sync(0xffffffffu, w, off);
                if (lane >= off) w += t;
            }
            warp_sums[lane] = w;
        }
        __syncthreads();
        int warp_off = (wid > 0) ? warp_sums[wid - 1] : 0;
        int excl = s_carry + x + warp_off - v;
        if (i < n) {
            g_rowptr[i] = excl;
            g_cursor[i] = excl;
            g_deg[i]    = 0;          // restore invariant for next call
        }
        __syncthreads();
        if (tid == 1023) s_carry += warp_sums[31];
        __syncthreads();
    }
    if (tid == 0) g_rowptr[n] = s_carry;
}

__global__ void scatter_kernel(const int* __restrict__ src,
                               const int* __restrict__ dst, int E) {
    int e = blockIdx.x * blockDim.x + threadIdx.x;
    if (e < E) {
        int pos = atomicAdd(&g_cursor[dst[e]], 1);
        g_csr_src[pos] = src[e];
    }
}

// ---------------------------------------------------------------------------
// Kernel 1: fused QKV projection, 2-stage cp.async pipelined TF32 GEMM.
// Block tile 128x128x32, warp tile 64x32, dynamic smem double buffers.
// smem holds raw fp32; tf32 cvt happens at fragment-load time.
// ---------------------------------------------------------------------------
#define GSTAGE 4608          // 128 * 36 words per tile buffer
#define GSMEM_BYTES (4 * GSTAGE * 4)   // As[2] + Bs[2]

__global__ __launch_bounds__(256) void qkv_gemm(
    const float* __restrict__ h,
    const float* __restrict__ Wq, const float* __restrict__ bq,
    const float* __restrict__ Wk, const float* __restrict__ bk,
    const float* __restrict__ Wv, const float* __restrict__ bv,
    int Nrows)
{
    extern __shared__ uint32_t sm[];   // [As0|As1|Bs0|Bs1], stride 36

    const int tid  = threadIdx.x;
    const int lane = tid & 31;
    const int warp = tid >> 5;
    const int wm = warp >> 2;
    const int wn = warp & 3;
    const int bm = blockIdx.x;
    const int bn = blockIdx.y;

    const float* W;  const float* bias;  float* target;
    if (bn < 2)      { W = Wq; bias = bq; target = g_Q; }
    else if (bn < 4) { W = Wk; bias = bk; target = g_K; }
    else             { W = Wv; bias = bv; target = g_V; }
    const int ncol0 = (bn & 1) * 128;

    float acc[4][4][4];
    #pragma unroll
    for (int i = 0; i < 4; i++)
        #pragma unroll
        for (int j = 0; j < 4; j++)
            #pragma unroll
            for (int k = 0; k < 4; k++) acc[i][j][k] = 0.0f;

    const int lr = tid >> 3;          // 0..31
    const int lc = (tid & 7) * 4;     // 0,4,..,28

    // per-thread smem byte addresses for cp.async
    const uint32_t smem_base = (uint32_t)__cvta_generic_to_shared(sm);

    // issue one stage of loads (A: rows may be OOB -> zero-fill via src_bytes=0)
    auto load_stage = [&](int kb, int s) {
        #pragma unroll
        for (int i = 0; i < 4; i++) {
            int r = lr + i * 32;
            int grow = bm * 128 + r;
            const float* gp = h + (size_t)grow * 256 + kb + lc;
            uint32_t sa = smem_base + (uint32_t)((s * GSTAGE + r * 36 + lc) * 4);
            cp_async16(sa, gp, (grow < Nrows) ? 16 : 0);
        }
        #pragma unroll
        for (int i = 0; i < 4; i++) {
            int r = lr + i * 32;
            const float* gp = W + (size_t)(ncol0 + r) * 256 + kb + lc;
            uint32_t sa = smem_base + (uint32_t)((2 * GSTAGE + s * GSTAGE + r * 36 + lc) * 4);
            cp_async16(sa, gp, 16);
        }
        asm volatile("cp.async.commit_group;" ::: "memory");
    };

    load_stage(0, 0);

    for (int it = 0; it < 8; it++) {
        const int p = it & 1;
        if (it + 1 < 8) {
            load_stage((it + 1) * 32, 1 - p);
            asm volatile("cp.async.wait_group 1;" ::: "memory");
        } else {
            asm volatile("cp.async.wait_group 0;" ::: "memory");
        }
        __syncthreads();

        const uint32_t* A = sm + p * GSTAGE;
        const uint32_t* B = sm + 2 * GSTAGE + p * GSTAGE;

        #pragma unroll
        for (int ks = 0; ks < 4; ks++) {
            const int k0 = ks * 8;
            uint32_t a[4][4], b[4][2];
            #pragma unroll
            for (int mt = 0; mt < 4; mt++) {
                int r = wm * 64 + mt * 16 + (lane >> 2);
                int c = k0 + (lane & 3);
                a[mt][0] = f2tf32(__uint_as_float(A[r * 36 + c]));
                a[mt][1] = f2tf32(__uint_as_float(A[(r + 8) * 36 + c]));
                a[mt][2] = f2tf32(__uint_as_float(A[r * 36 + c + 4]));
                a[mt][3] = f2tf32(__uint_as_float(A[(r + 8) * 36 + c + 4]));
            }
            #pragma unroll
            for (int nt = 0; nt < 4; nt++) {
                int n = wn * 32 + nt * 8 + (lane >> 2);
                int c = k0 + (lane & 3);
                b[nt][0] = f2tf32(__uint_as_float(B[n * 36 + c]));
                b[nt][1] = f2tf32(__uint_as_float(B[n * 36 + c + 4]));
            }
            #pragma unroll
            for (int mt = 0; mt < 4; mt++)
                #pragma unroll
                for (int nt = 0; nt < 4; nt++)
                    asm volatile(
                        "mma.sync.aligned.m16n8k8.row.col.f32.tf32.tf32.f32 "
                        "{%0,%1,%2,%3}, {%4,%5,%6,%7}, {%8,%9}, {%0,%1,%2,%3};"
                        : "+f"(acc[mt][nt][0]), "+f"(acc[mt][nt][1]),
                          "+f"(acc[mt][nt][2]), "+f"(acc[mt][nt][3])
                        : "r"(a[mt][0]), "r"(a[mt][1]), "r"(a[mt][2]), "r"(a[mt][3]),
                          "r"(b[nt][0]), "r"(b[nt][1]));
        }
        __syncthreads();
    }

    // epilogue: add bias, store
    #pragma unroll
    for (int mt = 0; mt < 4; mt++) {
        int r0 = wm * 64 + mt * 16 + (lane >> 2);
        #pragma unroll
        for (int nt = 0; nt < 4; nt++) {
            int c0 = wn * 32 + nt * 8 + (lane & 3) * 2;
            #pragma unroll
            for (int cc = 0; cc < 4; cc++) {
                int r = r0 + ((cc >= 2) ? 8 : 0);
                int c = c0 + (cc & 1);
                int grow = bm * 128 + r;
                if (grow < Nrows) {
                    int j = ncol0 + c;
                    target[(size_t)grow * 256 + j] = acc[mt][nt][cc] + bias[j];
                }
            }
        }
    }
}

// ---------------------------------------------------------------------------
// Kernel 2: single-pass fused attention.  One warp per destination node.
// ---------------------------------------------------------------------------
__global__ __launch_bounds__(256) void attn_fused(
    float* __restrict__ out, int n_nodes)
{
    const int node = (blockIdx.x * blockDim.x + threadIdx.x) >> 5;
    if (node >= n_nodes) return;
    const int lane = threadIdx.x & 31;
    const unsigned FULL = 0xffffffffu;
    const float inv = 0.17677669529663687f;   // 1/sqrt(32)

    const int beg = g_rowptr[node];
    const int end = g_rowptr[node + 1];

    const float4* Qr = (const float4*)(g_Q + (size_t)node * 256);
    const float4 q0 = Qr[lane];
    const float4 q1 = Qr[lane + 32];

    float4 acc0 = make_float4(0.f, 0.f, 0.f, 0.f);
    float4 acc1 = make_float4(0.f, 0.f, 0.f, 0.f);
    float z0 = 0.0f, z1 = 0.0f;

    for (int i = beg; i < end; i++) {
        const int s = g_csr_src[i];
        const float4* Kr = (const float4*)(g_K + (size_t)s * 256);
        const float4* Vr = (const float4*)(g_V + (size_t)s * 256);
        float4 k0 = Kr[lane];
        float4 k1 = Kr[lane + 32];
        float4 v0 = Vr[lane];
        float4 v1 = Vr[lane + 32];

        float p0 = k0.x * q0.x + k0.y * q0.y + k0.z * q0.z + k0.w * q0.w;
        float p1 = k1.x * q1.x + k1.y * q1.y + k1.z * q1.z + k1.w * q1.w;
        #pragma unroll
        for (int off = 4; off; off >>= 1) {
            p0 += __shfl_xor_sync(FULL, p0, off);
            p1 += __shfl_xor_sync(FULL, p1, off);
        }
        float sc0 = __expf(fminf(fmaxf(p0 * inv, -5.0f), 5.0f));
        float sc1 = __expf(fminf(fmaxf(p1 * inv, -5.0f), 5.0f));
        z0 += sc0;
        z1 += sc1;

        acc0.x += sc0 * v0.x; acc0.y += sc0 * v0.y;
        acc0.z += sc0 * v0.z; acc0.w += sc0 * v0.w;
        acc1.x += sc1 * v1.x; acc1.y += sc1 * v1.y;
        acc1.z += sc1 * v1.z; acc1.w += sc1 * v1.w;
    }

    const float rz0 = (z0 > 0.0f) ? 1.0f / z0 : 0.0f;
    const float rz1 = (z1 > 0.0f) ? 1.0f / z1 : 0.0f;
    acc0.x *= rz0; acc0.y *= rz0; acc0.z *= rz0; acc0.w *= rz0;
    acc1.x *= rz1; acc1.y *= rz1; acc1.z *= rz1; acc1.w *= rz1;

    float4* o = (float4*)(out + (size_t)node * 256);
    o[lane]      = acc0;
    o[lane + 32] = acc1;
}

// ---------------------------------------------------------------------------
extern "C" void kernel_launch(void* const* d_in, const int* in_sizes, int n_in,
                              void* d_out, int out_size)
{
    const float* h  = (const float*)d_in[0];
    const float* Wq = (const float*)d_in[1];
    const float* bq = (const float*)d_in[2];
    const float* Wk = (const float*)d_in[3];
    const float* bk = (const float*)d_in[4];
    const float* Wv = (const float*)d_in[5];
    const float* bv = (const float*)d_in[6];
    const int*   src = (const int*)d_in[7];
    const int*   dst = (const int*)d_in[8];
    float* out = (float*)d_out;

    const int N = in_sizes[0] / 256;   // 50000
    const int E = in_sizes[7];         // 800000

    // CSR build (single stream; R5 showed overlap regresses)
    hist_kernel   <<<(E + 255) / 256, 256>>>(dst, E);
    scan_kernel   <<<1, 1024>>>(N);
    scatter_kernel<<<(E + 255) / 256, 256>>>(src, dst, E);

    // QKV projections: pipelined TF32 GEMM with dynamic smem
    cudaFuncSetAttribute(qkv_gemm, cudaFuncAttributeMaxDynamicSharedMemorySize,
                         GSMEM_BYTES);
    dim3 grid((N + 127) / 128, 6);
    qkv_gemm<<<grid, 256, GSMEM_BYTES>>>(h, Wq, bq, Wk, bk, Wv, bv, N);

    attn_fused<<<(N * 32 + 255) / 256, 256>>>(out, N);
}